// round 2
// baseline (speedup 1.0000x reference)
#include <cuda_runtime.h>

#define N_NODES   50000
#define N_EDGES   1600000
#define NUM_GRAPHS 64
#define F   64
#define FIN 128

// Scratch (static __device__ globals; no allocation in kernel_launch)
__device__ __align__(16) float g_buf0[N_NODES * F];   // h1pre, then out1 (post-relu)
__device__ __align__(16) float g_buf1[N_NODES * F];   // agg1, then A
__device__ __align__(16) float g_G[NUM_GRAPHS * F];   // segment_sum(A, batch)
__device__ int   g_counts[NUM_GRAPHS];
__device__ int   g_is64;                              // 1 if index inputs are int64

// ---------------- dtype detection ----------------
// If edge_index is int64 (values < 2^31), every odd int32 word is 0.
// If it's already int32 random indices in [0,50000), odds of 64 zeros ~ 0.
__global__ void k_detect(const int* __restrict__ ei32) {
    if (threadIdx.x == 0) {
        int all0 = 1;
        for (int i = 0; i < 64; i++)
            if (ei32[2 * i + 1] != 0) { all0 = 0; break; }
        g_is64 = all0;
    }
}

__device__ __forceinline__ int load_idx(const int* p32, int i, int is64) {
    return is64 ? p32[2 * i] : p32[i];
}

// ---------------- zeroing ----------------
__global__ void k_zero_buf1() {
    int i = blockIdx.x * blockDim.x + threadIdx.x;
    if (i < N_NODES * F / 4)
        ((float4*)g_buf1)[i] = make_float4(0.f, 0.f, 0.f, 0.f);
}

__global__ void k_zero_G() {
    int i = threadIdx.x;  // 1024 threads, 4096 floats
    ((float4*)g_G)[i] = make_float4(0.f, 0.f, 0.f, 0.f);
}

// ---------------- GEMM1: g_buf0 = x[50000,128] @ W1[128,64] ----------------
__global__ void k_gemm1(const float* __restrict__ x, const float* __restrict__ W) {
    __shared__ float sW[FIN * F];
    int tid = threadIdx.x;
    for (int i = tid; i < FIN * F; i += 256) sW[i] = W[i];
    __syncthreads();
    int idx = blockIdx.x * 256 + tid;
    int r   = idx >> 4;
    int c4  = (idx & 15) << 2;
    if (r >= N_NODES) return;
    const float4* xr = (const float4*)(x + (size_t)r * FIN);
    float a0 = 0.f, a1 = 0.f, a2 = 0.f, a3 = 0.f;
#pragma unroll 8
    for (int k4 = 0; k4 < FIN / 4; k4++) {
        float4 xa = xr[k4];
        float4 w0 = *(const float4*)&sW[(k4 * 4 + 0) * F + c4];
        float4 w1 = *(const float4*)&sW[(k4 * 4 + 1) * F + c4];
        float4 w2 = *(const float4*)&sW[(k4 * 4 + 2) * F + c4];
        float4 w3 = *(const float4*)&sW[(k4 * 4 + 3) * F + c4];
        a0 += xa.x * w0.x + xa.y * w1.x + xa.z * w2.x + xa.w * w3.x;
        a1 += xa.x * w0.y + xa.y * w1.y + xa.z * w2.y + xa.w * w3.y;
        a2 += xa.x * w0.z + xa.y * w1.z + xa.z * w2.z + xa.w * w3.z;
        a3 += xa.x * w0.w + xa.y * w1.w + xa.z * w2.w + xa.w * w3.w;
    }
    *(float4*)&g_buf0[(size_t)r * F + c4] = make_float4(a0, a1, a2, a3);
}

// ---------------- edge scatter: g_buf1[tgt] += w * g_buf0[src]  ----------------
// 16 threads/edge, float4 gather + red.global.add.v4.f32
__global__ void k_scatter(const int* __restrict__ ei32,
                          const float* __restrict__ ew) {
    int t = blockIdx.x * blockDim.x + threadIdx.x;
    int e = t >> 4;
    if (e >= N_EDGES) return;
    int is64 = g_is64;
    int sub = (t & 15) << 2;
    // src = edge_index[0], tgt = edge_index[1] (tgt base at element offset N_EDGES)
    int s, d;
    if (is64) {
        s = ei32[2 * e];
        d = ei32[2 * N_EDGES + 2 * e];
    } else {
        s = ei32[e];
        d = ei32[N_EDGES + e];
    }
    float we = __ldg(&ew[e]);
    float4 v = *(const float4*)&g_buf0[(size_t)s * F + sub];
    float* p = &g_buf1[(size_t)d * F + sub];
    asm volatile("red.global.add.v4.f32 [%0], {%1,%2,%3,%4};"
                 :: "l"(p), "f"(v.x * we), "f"(v.y * we), "f"(v.z * we), "f"(v.w * we)
                 : "memory");
}

// ---------------- out1 = relu(agg1 + b1): g_buf0 = relu(g_buf1 + b1) ----------------
__global__ void k_bias_relu(const float* __restrict__ b) {
    int i = blockIdx.x * blockDim.x + threadIdx.x;
    if (i >= N_NODES * F / 4) return;
    float4 v  = ((const float4*)g_buf1)[i];
    int c4    = (i << 2) & (F - 1);
    float4 bb = *(const float4*)(b + c4);
    v.x = fmaxf(v.x + bb.x, 0.f);
    v.y = fmaxf(v.y + bb.y, 0.f);
    v.z = fmaxf(v.z + bb.z, 0.f);
    v.w = fmaxf(v.w + bb.w, 0.f);
    ((float4*)g_buf0)[i] = v;
}

// ---------------- embed = A @ W2 + b2  -> d_out[0 : N*F] ----------------
__global__ void k_gemm2(const float* __restrict__ W, const float* __restrict__ b,
                        float* __restrict__ out) {
    __shared__ float sW[F * F];
    int tid = threadIdx.x;
    for (int i = tid; i < F * F; i += 256) sW[i] = W[i];
    __syncthreads();
    int idx = blockIdx.x * 256 + tid;
    int r   = idx >> 4;
    int c4  = (idx & 15) << 2;
    if (r >= N_NODES) return;
    const float4* ar = (const float4*)&g_buf1[(size_t)r * F];
    float4 bb = *(const float4*)(b + c4);
    float a0 = bb.x, a1 = bb.y, a2 = bb.z, a3 = bb.w;
#pragma unroll 8
    for (int k4 = 0; k4 < F / 4; k4++) {
        float4 xa = ar[k4];
        float4 w0 = *(const float4*)&sW[(k4 * 4 + 0) * F + c4];
        float4 w1 = *(const float4*)&sW[(k4 * 4 + 1) * F + c4];
        float4 w2 = *(const float4*)&sW[(k4 * 4 + 2) * F + c4];
        float4 w3 = *(const float4*)&sW[(k4 * 4 + 3) * F + c4];
        a0 += xa.x * w0.x + xa.y * w1.x + xa.z * w2.x + xa.w * w3.x;
        a1 += xa.x * w0.y + xa.y * w1.y + xa.z * w2.y + xa.w * w3.y;
        a2 += xa.x * w0.z + xa.y * w1.z + xa.z * w2.z + xa.w * w3.z;
        a3 += xa.x * w0.w + xa.y * w1.w + xa.z * w2.w + xa.w * w3.w;
    }
    *(float4*)&out[(size_t)r * F + c4] = make_float4(a0, a1, a2, a3);
}

// ---------------- g_G = segment_sum(A, batch)  (batch is sorted) ----------------
__global__ void k_reduce(const int* __restrict__ b32) {
    int is64 = g_is64;
    int c  = threadIdx.x & 63;
    int rl = threadIdx.x >> 6;          // 0..3
    int base = blockIdx.x * 512;
    float acc = 0.f;
    int cur = -1;
    for (int j = 0; j < 128; j++) {
        int r = base + rl + (j << 2);
        if (r >= N_NODES) break;
        int g = load_idx(b32, r, is64);
        if (g != cur) {
            if (cur >= 0) atomicAdd(&g_G[cur * F + c], acc);
            cur = g; acc = 0.f;
        }
        acc += g_buf1[(size_t)r * F + c];
    }
    if (cur >= 0) atomicAdd(&g_G[cur * F + c], acc);
}

// ---------------- counts[g] = #nodes in graph g (binary search, batch sorted) ----------------
__global__ void k_counts(const int* __restrict__ b32) {
    int is64 = g_is64;
    int g = threadIdx.x;
    if (g >= NUM_GRAPHS) return;
    int v0 = g, v1 = g + 1;
    int lo = 0, hi = N_NODES;
    while (lo < hi) { int m = (lo + hi) >> 1; if (load_idx(b32, m, is64) < v0) lo = m + 1; else hi = m; }
    int a = lo;
    lo = 0; hi = N_NODES;
    while (lo < hi) { int m = (lo + hi) >> 1; if (load_idx(b32, m, is64) < v1) lo = m + 1; else hi = m; }
    g_counts[g] = lo - a;
}

// ---------------- graph_embed = G @ W3 + counts * b3 -> d_out[N*F : +4096] ----------------
__global__ void k_gout(const float* __restrict__ W3, const float* __restrict__ b3,
                       float* __restrict__ out) {
    __shared__ float sG[F];
    int g = blockIdx.x, j = threadIdx.x;
    sG[j] = g_G[g * F + j];
    __syncthreads();
    float acc = (float)g_counts[g] * b3[j];
#pragma unroll 8
    for (int k = 0; k < F; k++) acc += sG[k] * W3[k * F + j];
    out[g * F + j] = acc;
}

extern "C" void kernel_launch(void* const* d_in, const int* in_sizes, int n_in,
                              void* d_out, int out_size) {
    const float* x     = (const float*)d_in[0];
    const int*   ei32  = (const int*)d_in[1];
    const float* ew    = (const float*)d_in[2];
    const int*   b32   = (const int*)d_in[3];
    const float* W1    = (const float*)d_in[4];
    const float* b1    = (const float*)d_in[5];
    const float* W2    = (const float*)d_in[6];
    const float* b2    = (const float*)d_in[7];
    const float* W3    = (const float*)d_in[8];
    const float* b3    = (const float*)d_in[9];
    float* out = (float*)d_out;

    const int ZG = (N_NODES * F / 4 + 255) / 256;       // 3125
    const int SG = (N_EDGES * 16 + 255) / 256;          // 100000

    k_detect<<<1, 32>>>(ei32);
    k_zero_buf1<<<ZG, 256>>>();
    k_gemm1<<<(N_NODES * 16 + 255) / 256, 256>>>(x, W1);     // g_buf0 = x@W1
    k_scatter<<<SG, 256>>>(ei32, ew);                        // g_buf1 = agg(g_buf0)
    k_bias_relu<<<ZG, 256>>>(b1);                            // g_buf0 = relu(g_buf1+b1)
    k_zero_buf1<<<ZG, 256>>>();
    k_scatter<<<SG, 256>>>(ei32, ew);                        // g_buf1 = A = agg(out1)
    k_gemm2<<<(N_NODES * 16 + 255) / 256, 256>>>(W2, b2, out);  // embed
    k_zero_G<<<1, 1024>>>();
    k_reduce<<<(N_NODES + 511) / 512, 256>>>(b32);           // g_G = segsum(A, batch)
    k_counts<<<1, 64>>>(b32);
    k_gout<<<NUM_GRAPHS, F>>>(W3, b3, out + (size_t)N_NODES * F);  // graph_embed
}

// round 3
// speedup vs baseline: 1.4064x; 1.4064x over previous
#include <cuda_runtime.h>

#define N_NODES   50000
#define N_EDGES   1600000
#define NUM_GRAPHS 64
#define F   64
#define FIN 128
#define NB_SCAN   196          // ceil(50000/256)

// ---------------- scratch ----------------
__device__ __align__(16) float g_buf0[N_NODES * F];   // h1, then A
__device__ __align__(16) float g_buf1[N_NODES * F];   // out1 (post-relu)
__device__ __align__(16) float g_G[NUM_GRAPHS * F];
__device__ int   g_counts[NUM_GRAPHS];
__device__ int   g_is64;
__device__ int   g_deg[N_NODES];
__device__ int   g_rowptr[N_NODES + 1];
__device__ int   g_cursor[N_NODES];
__device__ int   g_bsum[256];
__device__ __align__(16) uint2 g_csr[N_EDGES];        // (src, bits(w)) sorted by tgt

// ---------------- dtype detection ----------------
__global__ void k_detect(const int* __restrict__ ei32) {
    if (threadIdx.x == 0) {
        int all0 = 1;
        for (int i = 0; i < 64; i++)
            if (ei32[2 * i + 1] != 0) { all0 = 0; break; }
        g_is64 = all0;
    }
}

// ---------------- zero deg + G ----------------
__global__ void k_zero_meta() {
    int i = blockIdx.x * blockDim.x + threadIdx.x;
    if (i < N_NODES) g_deg[i] = 0;
    if (i < NUM_GRAPHS * F) g_G[i] = 0.f;
}

// ---------------- degree histogram ----------------
__global__ void k_hist(const int* __restrict__ ei32) {
    int e = blockIdx.x * blockDim.x + threadIdx.x;
    if (e >= N_EDGES) return;
    int is64 = g_is64;
    int d = is64 ? ei32[2 * N_EDGES + 2 * e] : ei32[N_EDGES + e];
    atomicAdd(&g_deg[d], 1);
}

// ---------------- scan step 1: per-block sums ----------------
__global__ void k_s1() {
    __shared__ int s[256];
    int tid = threadIdx.x;
    int i = blockIdx.x * 256 + tid;
    s[tid] = (i < N_NODES) ? g_deg[i] : 0;
    __syncthreads();
    for (int o = 128; o > 0; o >>= 1) {
        if (tid < o) s[tid] += s[tid + o];
        __syncthreads();
    }
    if (tid == 0) g_bsum[blockIdx.x] = s[0];
}

// ---------------- scan step 2: scan of block sums ----------------
__global__ void k_s2() {
    __shared__ int s[256];
    int tid = threadIdx.x;
    int v = (tid < NB_SCAN) ? g_bsum[tid] : 0;
    s[tid] = v;
    __syncthreads();
    for (int o = 1; o < 256; o <<= 1) {
        int t = (tid >= o) ? s[tid - o] : 0;
        __syncthreads();
        s[tid] += t;
        __syncthreads();
    }
    g_bsum[tid] = s[tid] - v;   // exclusive
}

// ---------------- scan step 3: local scan + offset -> rowptr, cursor ----------------
__global__ void k_s3() {
    __shared__ int s[256];
    int tid = threadIdx.x;
    int i = blockIdx.x * 256 + tid;
    int v = (i < N_NODES) ? g_deg[i] : 0;
    s[tid] = v;
    __syncthreads();
    for (int o = 1; o < 256; o <<= 1) {
        int t = (tid >= o) ? s[tid - o] : 0;
        __syncthreads();
        s[tid] += t;
        __syncthreads();
    }
    if (i < N_NODES) {
        int excl = s[tid] - v + g_bsum[blockIdx.x];
        g_rowptr[i] = excl;
        g_cursor[i] = excl;
    }
    if (i == 0) g_rowptr[N_NODES] = N_EDGES;
}

// ---------------- CSR fill ----------------
__global__ void k_fill(const int* __restrict__ ei32, const float* __restrict__ ew) {
    int e = blockIdx.x * blockDim.x + threadIdx.x;
    if (e >= N_EDGES) return;
    int is64 = g_is64;
    int s, d;
    if (is64) { s = ei32[2 * e]; d = ei32[2 * N_EDGES + 2 * e]; }
    else      { s = ei32[e];     d = ei32[N_EDGES + e]; }
    int pos = atomicAdd(&g_cursor[d], 1);
    g_csr[pos] = make_uint2((unsigned)s, __float_as_uint(ew[e]));
}

// ---------------- CSR gather: out[n] = post( sum_e w_e * in[src_e] ) ----------------
// 16 threads per node (one float4 column each), 16 nodes per 256-thread block.
// Edge entries staged into smem in tiles (contiguous across the block's nodes).
__global__ void k_gather(const float* __restrict__ in, float* __restrict__ out,
                         const float* __restrict__ bias, int relu) {
    __shared__ uint2 tile[1024];
    int tid  = threadIdx.x;
    int node0 = blockIdx.x * 16;
    int n    = node0 + (tid >> 4);
    int sub  = (tid & 15) << 2;

    int e_begin = __ldg(&g_rowptr[node0]);
    int e_end   = __ldg(&g_rowptr[node0 + 16]);
    int my_s    = __ldg(&g_rowptr[n]);
    int my_e    = __ldg(&g_rowptr[n + 1]);

    float4 acc = make_float4(0.f, 0.f, 0.f, 0.f);

    for (int base = e_begin; base < e_end; base += 1024) {
        int cnt = min(1024, e_end - base);
        __syncthreads();
        for (int i = tid; i < cnt; i += 256) tile[i] = g_csr[base + i];
        __syncthreads();
        int lo = max(my_s, base);
        int hi = min(my_e, base + cnt);
        int e = lo;
        for (; e + 1 < hi; e += 2) {
            uint2 p0 = tile[e - base];
            uint2 p1 = tile[e + 1 - base];
            float4 v0 = *(const float4*)&in[p0.x * F + sub];
            float4 v1 = *(const float4*)&in[p1.x * F + sub];
            float w0 = __uint_as_float(p0.y);
            float w1 = __uint_as_float(p1.y);
            acc.x += w0 * v0.x + w1 * v1.x;
            acc.y += w0 * v0.y + w1 * v1.y;
            acc.z += w0 * v0.z + w1 * v1.z;
            acc.w += w0 * v0.w + w1 * v1.w;
        }
        if (e < hi) {
            uint2 p = tile[e - base];
            float4 v = *(const float4*)&in[p.x * F + sub];
            float w = __uint_as_float(p.y);
            acc.x += w * v.x; acc.y += w * v.y;
            acc.z += w * v.z; acc.w += w * v.w;
        }
    }

    if (bias) {
        float4 bb = *(const float4*)&bias[sub];
        acc.x += bb.x; acc.y += bb.y; acc.z += bb.z; acc.w += bb.w;
    }
    if (relu) {
        acc.x = fmaxf(acc.x, 0.f); acc.y = fmaxf(acc.y, 0.f);
        acc.z = fmaxf(acc.z, 0.f); acc.w = fmaxf(acc.w, 0.f);
    }
    *(float4*)&out[n * F + sub] = acc;
}

// ---------------- register-blocked GEMM: out[N,64] = X[N,K] @ W[K,64] (+bias) ----------------
// 128 threads, tile 64 rows x 64 cols; thread = 4 rows x 8 cols.
template<int K>
__global__ void k_gemm(const float* __restrict__ X, const float* __restrict__ W,
                       const float* __restrict__ bias, float* __restrict__ out) {
    __shared__ float sx[64 * 68];   // [k][row] transposed, pad 68
    __shared__ float sw[64 * 68];   // [k][col] pad 68
    int tid = threadIdx.x;
    int tx = tid & 7;        // col group: cols tx*8..+7
    int ty = tid >> 3;       // row group: rows ty*4..+3
    int row0 = blockIdx.x * 64;

    float acc[4][8];
#pragma unroll
    for (int i = 0; i < 4; i++)
#pragma unroll
        for (int j = 0; j < 8; j++) acc[i][j] = 0.f;

    for (int kt = 0; kt < K; kt += 64) {
        __syncthreads();
        // stage X tile transposed: sx[k][r] = X[row0+r][kt+k]
        for (int i = tid; i < 64 * 64; i += 128) {
            int r = i >> 6, k = i & 63;
            float v = (row0 + r < N_NODES) ? X[(size_t)(row0 + r) * K + kt + k] : 0.f;
            sx[k * 68 + r] = v;
        }
        // stage W tile: sw[k][c] = W[kt+k][c]
        for (int i = tid; i < 64 * 64; i += 128) {
            int k = i >> 6, c = i & 63;
            sw[k * 68 + c] = W[(size_t)(kt + k) * F + c];
        }
        __syncthreads();
#pragma unroll
        for (int k = 0; k < 64; k++) {
            float4 xa = *(const float4*)&sx[k * 68 + ty * 4];
            float4 wa = *(const float4*)&sw[k * 68 + tx * 8];
            float4 wb = *(const float4*)&sw[k * 68 + tx * 8 + 4];
            float xr[4] = {xa.x, xa.y, xa.z, xa.w};
            float wc[8] = {wa.x, wa.y, wa.z, wa.w, wb.x, wb.y, wb.z, wb.w};
#pragma unroll
            for (int i = 0; i < 4; i++)
#pragma unroll
                for (int j = 0; j < 8; j++)
                    acc[i][j] += xr[i] * wc[j];
        }
    }

    float bb[8];
#pragma unroll
    for (int j = 0; j < 8; j++) bb[j] = bias ? bias[tx * 8 + j] : 0.f;

#pragma unroll
    for (int i = 0; i < 4; i++) {
        int r = row0 + ty * 4 + i;
        if (r >= N_NODES) continue;
        float4 o0 = make_float4(acc[i][0] + bb[0], acc[i][1] + bb[1],
                                acc[i][2] + bb[2], acc[i][3] + bb[3]);
        float4 o1 = make_float4(acc[i][4] + bb[4], acc[i][5] + bb[5],
                                acc[i][6] + bb[6], acc[i][7] + bb[7]);
        *(float4*)&out[(size_t)r * F + tx * 8]     = o0;
        *(float4*)&out[(size_t)r * F + tx * 8 + 4] = o1;
    }
}

// ---------------- g_G = segment_sum(A=g_buf0, batch)  (batch sorted) ----------------
__global__ void k_reduce(const int* __restrict__ b32) {
    int is64 = g_is64;
    int c  = threadIdx.x & 63;
    int rl = threadIdx.x >> 6;
    int base = blockIdx.x * 512;
    float acc = 0.f;
    int cur = -1;
    for (int j = 0; j < 128; j++) {
        int r = base + rl + (j << 2);
        if (r >= N_NODES) break;
        int g = is64 ? b32[2 * r] : b32[r];
        if (g != cur) {
            if (cur >= 0) atomicAdd(&g_G[cur * F + c], acc);
            cur = g; acc = 0.f;
        }
        acc += g_buf0[(size_t)r * F + c];
    }
    if (cur >= 0) atomicAdd(&g_G[cur * F + c], acc);
}

// ---------------- counts (binary search over sorted batch) ----------------
__global__ void k_counts(const int* __restrict__ b32) {
    int is64 = g_is64;
    int g = threadIdx.x;
    if (g >= NUM_GRAPHS) return;
    int lo = 0, hi = N_NODES;
    while (lo < hi) { int m = (lo + hi) >> 1; int v = is64 ? b32[2*m] : b32[m]; if (v < g) lo = m + 1; else hi = m; }
    int a = lo;
    lo = 0; hi = N_NODES;
    while (lo < hi) { int m = (lo + hi) >> 1; int v = is64 ? b32[2*m] : b32[m]; if (v < g + 1) lo = m + 1; else hi = m; }
    g_counts[g] = lo - a;
}

// ---------------- graph_embed = G @ W3 + counts*b3 ----------------
__global__ void k_gout(const float* __restrict__ W3, const float* __restrict__ b3,
                       float* __restrict__ out) {
    __shared__ float sG[F];
    int g = blockIdx.x, j = threadIdx.x;
    sG[j] = g_G[g * F + j];
    __syncthreads();
    float acc = (float)g_counts[g] * b3[j];
#pragma unroll 8
    for (int k = 0; k < F; k++) acc += sG[k] * W3[k * F + j];
    out[g * F + j] = acc;
}

extern "C" void kernel_launch(void* const* d_in, const int* in_sizes, int n_in,
                              void* d_out, int out_size) {
    const float* x    = (const float*)d_in[0];
    const int*   ei32 = (const int*)d_in[1];
    const float* ew   = (const float*)d_in[2];
    const int*   b32  = (const int*)d_in[3];
    const float* W1   = (const float*)d_in[4];
    const float* b1   = (const float*)d_in[5];
    const float* W2   = (const float*)d_in[6];
    const float* b2   = (const float*)d_in[7];
    const float* W3   = (const float*)d_in[8];
    const float* b3   = (const float*)d_in[9];
    float* out = (float*)d_out;

    float *buf0, *buf1;
    cudaGetSymbolAddress((void**)&buf0, g_buf0);
    cudaGetSymbolAddress((void**)&buf1, g_buf1);

    const int EG = (N_EDGES + 255) / 256;     // 6250
    const int GG = (N_NODES + 63) / 64;       // 782

    k_detect<<<1, 32>>>(ei32);
    k_zero_meta<<<(N_NODES + 255) / 256, 256>>>();
    k_hist<<<EG, 256>>>(ei32);
    k_s1<<<NB_SCAN, 256>>>();
    k_s2<<<1, 256>>>();
    k_s3<<<NB_SCAN, 256>>>();
    k_fill<<<EG, 256>>>(ei32, ew);

    k_gemm<FIN><<<GG, 128>>>(x, W1, nullptr, buf0);          // h1 = x@W1
    k_gather<<<N_NODES / 16, 256>>>(buf0, buf1, b1, 1);      // out1 = relu(agg(h1)+b1)
    k_gather<<<N_NODES / 16, 256>>>(buf1, buf0, nullptr, 0); // A = agg(out1)
    k_gemm<F><<<GG, 128>>>(buf0, W2, b2, out);               // embed = A@W2+b2

    k_reduce<<<(N_NODES + 511) / 512, 256>>>(b32);           // G = segsum(A,batch)
    k_counts<<<1, 64>>>(b32);
    k_gout<<<NUM_GRAPHS, F>>>(W3, b3, out + (size_t)N_NODES * F);
}

// round 4
// speedup vs baseline: 1.6241x; 1.1548x over previous
#include <cuda_runtime.h>
#include <cuda_fp16.h>

#define N_NODES   50000
#define N_EDGES   1600000
#define NUM_GRAPHS 64
#define F   64
#define FIN 128
#define NB_SCAN   196          // ceil(50000/256)

// ---------------- scratch ----------------
__device__ __align__(16) __half g_h [N_NODES * F];   // h1 = x@W1 (fp16 storage)
__device__ __align__(16) __half g_o1[N_NODES * F];   // out1 = relu(agg(h1)+b1)
__device__ __align__(16) __half g_A [N_NODES * F];   // A = agg(out1)
__device__ __align__(16) float  g_G[NUM_GRAPHS * F];
__device__ int      g_is64;
__device__ int      g_deg[N_NODES];
__device__ int      g_rowptr[N_NODES + 1];
__device__ int      g_cursor[N_NODES];
__device__ int      g_bsum[256];
__device__ unsigned g_csr[N_EDGES];                  // (src<<16) | half_bits(w)

// ---------------- zero meta + dtype detect (fused) ----------------
__global__ void k_zero_meta(const int* __restrict__ ei32) {
    int i = blockIdx.x * 256 + threadIdx.x;
    if (i < N_NODES) g_deg[i] = 0;
    if (i < NUM_GRAPHS * F) g_G[i] = 0.f;
    if (i == 0) {
        // int64 indices < 2^31 -> every odd int32 word is 0
        int all0 = 1;
        for (int j = 0; j < 64; j++)
            if (ei32[2 * j + 1] != 0) { all0 = 0; break; }
        g_is64 = all0;
    }
}

// ---------------- degree histogram ----------------
__global__ void k_hist(const int* __restrict__ ei32) {
    int e = blockIdx.x * blockDim.x + threadIdx.x;
    if (e >= N_EDGES) return;
    int is64 = g_is64;
    int d = is64 ? ei32[2 * N_EDGES + 2 * e] : ei32[N_EDGES + e];
    atomicAdd(&g_deg[d], 1);
}

// ---------------- scan step 1: per-block sums ----------------
__global__ void k_s1() {
    __shared__ int s[256];
    int tid = threadIdx.x;
    int i = blockIdx.x * 256 + tid;
    s[tid] = (i < N_NODES) ? g_deg[i] : 0;
    __syncthreads();
    for (int o = 128; o > 0; o >>= 1) {
        if (tid < o) s[tid] += s[tid + o];
        __syncthreads();
    }
    if (tid == 0) g_bsum[blockIdx.x] = s[0];
}

// ---------------- scan step 2: scan of block sums ----------------
__global__ void k_s2() {
    __shared__ int s[256];
    int tid = threadIdx.x;
    int v = (tid < NB_SCAN) ? g_bsum[tid] : 0;
    s[tid] = v;
    __syncthreads();
    for (int o = 1; o < 256; o <<= 1) {
        int t = (tid >= o) ? s[tid - o] : 0;
        __syncthreads();
        s[tid] += t;
        __syncthreads();
    }
    g_bsum[tid] = s[tid] - v;   // exclusive
}

// ---------------- scan step 3: local scan + offset -> rowptr, cursor ----------------
__global__ void k_s3() {
    __shared__ int s[256];
    int tid = threadIdx.x;
    int i = blockIdx.x * 256 + tid;
    int v = (i < N_NODES) ? g_deg[i] : 0;
    s[tid] = v;
    __syncthreads();
    for (int o = 1; o < 256; o <<= 1) {
        int t = (tid >= o) ? s[tid - o] : 0;
        __syncthreads();
        s[tid] += t;
        __syncthreads();
    }
    if (i < N_NODES) {
        int excl = s[tid] - v + g_bsum[blockIdx.x];
        g_rowptr[i] = excl;
        g_cursor[i] = excl;
    }
    if (i == 0) g_rowptr[N_NODES] = N_EDGES;
}

// ---------------- CSR fill: pack (src:16 | w:fp16) ----------------
__global__ void k_fill(const int* __restrict__ ei32, const float* __restrict__ ew) {
    int e = blockIdx.x * blockDim.x + threadIdx.x;
    if (e >= N_EDGES) return;
    int is64 = g_is64;
    int s, d;
    if (is64) { s = ei32[2 * e]; d = ei32[2 * N_EDGES + 2 * e]; }
    else      { s = ei32[e];     d = ei32[N_EDGES + e]; }
    int pos = atomicAdd(&g_cursor[d], 1);
    unsigned hw = (unsigned)__half_as_ushort(__float2half_rn(__ldg(&ew[e])));
    g_csr[pos] = ((unsigned)s << 16) | hw;
}

// ---------------- fp16 accumulate helper ----------------
__device__ __forceinline__ void hacc8(float* acc, uint4 raw, float w) {
    __half2* h = (__half2*)&raw;
#pragma unroll
    for (int q = 0; q < 4; q++) {
        float2 f = __half22float2(h[q]);
        acc[2 * q]     += w * f.x;
        acc[2 * q + 1] += w * f.y;
    }
}

// ---------------- CSR gather: out[n] = post( sum_e w_e * in[src_e] ) ----------------
// 8 threads/node (8 halves = 16B each), 32 nodes per 256-thread block.
__global__ void k_gather(const __half* __restrict__ in, __half* __restrict__ out,
                         const float* __restrict__ bias, int relu) {
    __shared__ unsigned tile[2048];
    int tid   = threadIdx.x;
    int node0 = blockIdx.x * 32;
    int n     = node0 + (tid >> 3);
    int sub   = (tid & 7) * 8;     // col offset in halves
    int hi_node = min(node0 + 32, N_NODES);

    int e_begin = __ldg(&g_rowptr[node0]);
    int e_end   = __ldg(&g_rowptr[hi_node]);
    int my_s, my_e;
    if (n < N_NODES) { my_s = __ldg(&g_rowptr[n]); my_e = __ldg(&g_rowptr[n + 1]); }
    else             { my_s = my_e = e_begin; }

    float acc[8];
#pragma unroll
    for (int j = 0; j < 8; j++) acc[j] = 0.f;

    for (int base = e_begin; base < e_end; base += 2048) {
        int cnt = min(2048, e_end - base);
        __syncthreads();
        for (int i = tid; i < cnt; i += 256) tile[i] = g_csr[base + i];
        __syncthreads();
        int lo = max(my_s, base);
        int hi = min(my_e, base + cnt);
        int e = lo;
        for (; e + 1 < hi; e += 2) {
            unsigned p0 = tile[e - base];
            unsigned p1 = tile[e + 1 - base];
            uint4 r0 = *(const uint4*)&in[(size_t)(p0 >> 16) * F + sub];
            uint4 r1 = *(const uint4*)&in[(size_t)(p1 >> 16) * F + sub];
            float w0 = __half2float(__ushort_as_half((unsigned short)(p0 & 0xffffu)));
            float w1 = __half2float(__ushort_as_half((unsigned short)(p1 & 0xffffu)));
            hacc8(acc, r0, w0);
            hacc8(acc, r1, w1);
        }
        if (e < hi) {
            unsigned p = tile[e - base];
            uint4 r = *(const uint4*)&in[(size_t)(p >> 16) * F + sub];
            float w = __half2float(__ushort_as_half((unsigned short)(p & 0xffffu)));
            hacc8(acc, r, w);
        }
    }

    if (n < N_NODES) {
        if (bias) {
#pragma unroll
            for (int j = 0; j < 8; j++) acc[j] += __ldg(&bias[sub + j]);
        }
        if (relu) {
#pragma unroll
            for (int j = 0; j < 8; j++) acc[j] = fmaxf(acc[j], 0.f);
        }
        __half2 o[4];
#pragma unroll
        for (int q = 0; q < 4; q++)
            o[q] = __floats2half2_rn(acc[2 * q], acc[2 * q + 1]);
        *(uint4*)&out[(size_t)n * F + sub] = *(uint4*)o;
    }
}

// ---------------- GEMM1: g_h = half(x[50000,128] @ W1[128,64]) ----------------
// 128 threads, tile 64x64, thread = 4 rows x 8 cols.
__global__ void k_gemm1(const float* __restrict__ X, const float* __restrict__ W) {
    __shared__ float sx[64 * 68];
    __shared__ float sw[64 * 68];
    int tid = threadIdx.x;
    int tx = tid & 7;
    int ty = tid >> 3;
    int row0 = blockIdx.x * 64;

    float acc[4][8];
#pragma unroll
    for (int i = 0; i < 4; i++)
#pragma unroll
        for (int j = 0; j < 8; j++) acc[i][j] = 0.f;

    for (int kt = 0; kt < FIN; kt += 64) {
        __syncthreads();
        for (int i = tid; i < 64 * 64; i += 128) {
            int r = i >> 6, k = i & 63;
            float v = (row0 + r < N_NODES) ? X[(size_t)(row0 + r) * FIN + kt + k] : 0.f;
            sx[k * 68 + r] = v;
        }
        for (int i = tid; i < 64 * 64; i += 128) {
            int k = i >> 6, c = i & 63;
            sw[k * 68 + c] = W[(size_t)(kt + k) * F + c];
        }
        __syncthreads();
#pragma unroll
        for (int k = 0; k < 64; k++) {
            float4 xa = *(const float4*)&sx[k * 68 + ty * 4];
            float4 wa = *(const float4*)&sw[k * 68 + tx * 8];
            float4 wb = *(const float4*)&sw[k * 68 + tx * 8 + 4];
            float xr[4] = {xa.x, xa.y, xa.z, xa.w};
            float wc[8] = {wa.x, wa.y, wa.z, wa.w, wb.x, wb.y, wb.z, wb.w};
#pragma unroll
            for (int i = 0; i < 4; i++)
#pragma unroll
                for (int j = 0; j < 8; j++)
                    acc[i][j] += xr[i] * wc[j];
        }
    }

#pragma unroll
    for (int i = 0; i < 4; i++) {
        int r = row0 + ty * 4 + i;
        if (r >= N_NODES) continue;
        __half2 o[4];
#pragma unroll
        for (int q = 0; q < 4; q++)
            o[q] = __floats2half2_rn(acc[i][2 * q], acc[i][2 * q + 1]);
        *(uint4*)&g_h[(size_t)r * F + tx * 8] = *(uint4*)o;
    }
}

// ---------------- GEMM2: out = A(half)[50000,64] @ W2[64,64] + b2 (fp32 out) ----------------
__global__ void k_gemm2(const float* __restrict__ W, const float* __restrict__ bias,
                        float* __restrict__ out) {
    __shared__ float sx[64 * 68];
    __shared__ float sw[64 * 68];
    int tid = threadIdx.x;
    int tx = tid & 7;
    int ty = tid >> 3;
    int row0 = blockIdx.x * 64;

    // stage A tile (half -> float, transposed): 64 rows x 8 kgroups of 8
    for (int t = tid; t < 512; t += 128) {
        int r = t >> 3, k8 = (t & 7) * 8;
        uint4 raw;
        if (row0 + r < N_NODES) raw = *(const uint4*)&g_A[(size_t)(row0 + r) * F + k8];
        else raw = make_uint4(0, 0, 0, 0);
        __half2* h = (__half2*)&raw;
#pragma unroll
        for (int q = 0; q < 4; q++) {
            float2 f = __half22float2(h[q]);
            sx[(k8 + 2 * q) * 68 + r]     = f.x;
            sx[(k8 + 2 * q + 1) * 68 + r] = f.y;
        }
    }
    for (int i = tid; i < 64 * 64; i += 128) {
        int k = i >> 6, c = i & 63;
        sw[k * 68 + c] = W[(size_t)k * F + c];
    }
    __syncthreads();

    float acc[4][8];
#pragma unroll
    for (int i = 0; i < 4; i++)
#pragma unroll
        for (int j = 0; j < 8; j++) acc[i][j] = 0.f;

#pragma unroll
    for (int k = 0; k < 64; k++) {
        float4 xa = *(const float4*)&sx[k * 68 + ty * 4];
        float4 wa = *(const float4*)&sw[k * 68 + tx * 8];
        float4 wb = *(const float4*)&sw[k * 68 + tx * 8 + 4];
        float xr[4] = {xa.x, xa.y, xa.z, xa.w};
        float wc[8] = {wa.x, wa.y, wa.z, wa.w, wb.x, wb.y, wb.z, wb.w};
#pragma unroll
        for (int i = 0; i < 4; i++)
#pragma unroll
            for (int j = 0; j < 8; j++)
                acc[i][j] += xr[i] * wc[j];
    }

    float bb[8];
#pragma unroll
    for (int j = 0; j < 8; j++) bb[j] = bias[tx * 8 + j];

#pragma unroll
    for (int i = 0; i < 4; i++) {
        int r = row0 + ty * 4 + i;
        if (r >= N_NODES) continue;
        float4 o0 = make_float4(acc[i][0] + bb[0], acc[i][1] + bb[1],
                                acc[i][2] + bb[2], acc[i][3] + bb[3]);
        float4 o1 = make_float4(acc[i][4] + bb[4], acc[i][5] + bb[5],
                                acc[i][6] + bb[6], acc[i][7] + bb[7]);
        *(float4*)&out[(size_t)r * F + tx * 8]     = o0;
        *(float4*)&out[(size_t)r * F + tx * 8 + 4] = o1;
    }
}

// ---------------- g_G = segment_sum(A, batch)  (batch sorted) ----------------
__global__ void k_reduce(const int* __restrict__ b32) {
    int is64 = g_is64;
    int c  = threadIdx.x & 63;
    int rl = threadIdx.x >> 6;
    int base = blockIdx.x * 512;
    float acc = 0.f;
    int cur = -1;
    for (int j = 0; j < 128; j++) {
        int r = base + rl + (j << 2);
        if (r >= N_NODES) break;
        int g = is64 ? b32[2 * r] : b32[r];
        if (g != cur) {
            if (cur >= 0) atomicAdd(&g_G[cur * F + c], acc);
            cur = g; acc = 0.f;
        }
        acc += __half2float(g_A[(size_t)r * F + c]);
    }
    if (cur >= 0) atomicAdd(&g_G[cur * F + c], acc);
}

// ---------------- graph_embed = G @ W3 + counts*b3 (counts fused via bsearch) ----------------
__global__ void k_gout(const int* __restrict__ b32, const float* __restrict__ W3,
                       const float* __restrict__ b3, float* __restrict__ out) {
    __shared__ float sG[F];
    __shared__ int scount;
    int g = blockIdx.x, j = threadIdx.x;
    sG[j] = g_G[g * F + j];
    if (j == 0) {
        int is64 = g_is64;
        int lo = 0, hi = N_NODES;
        while (lo < hi) { int m = (lo + hi) >> 1; int v = is64 ? b32[2 * m] : b32[m]; if (v < g) lo = m + 1; else hi = m; }
        int a = lo;
        lo = 0; hi = N_NODES;
        while (lo < hi) { int m = (lo + hi) >> 1; int v = is64 ? b32[2 * m] : b32[m]; if (v < g + 1) lo = m + 1; else hi = m; }
        scount = lo - a;
    }
    __syncthreads();
    float acc = (float)scount * b3[j];
#pragma unroll 8
    for (int k = 0; k < F; k++) acc += sG[k] * W3[k * F + j];
    out[g * F + j] = acc;
}

extern "C" void kernel_launch(void* const* d_in, const int* in_sizes, int n_in,
                              void* d_out, int out_size) {
    const float* x    = (const float*)d_in[0];
    const int*   ei32 = (const int*)d_in[1];
    const float* ew   = (const float*)d_in[2];
    const int*   b32  = (const int*)d_in[3];
    const float* W1   = (const float*)d_in[4];
    const float* b1   = (const float*)d_in[5];
    const float* W2   = (const float*)d_in[6];
    const float* b2   = (const float*)d_in[7];
    const float* W3   = (const float*)d_in[8];
    const float* b3   = (const float*)d_in[9];
    float* out = (float*)d_out;

    __half *h, *o1, *A;
    cudaGetSymbolAddress((void**)&h,  g_h);
    cudaGetSymbolAddress((void**)&o1, g_o1);
    cudaGetSymbolAddress((void**)&A,  g_A);

    const int EG = (N_EDGES + 255) / 256;     // 6250
    const int GG = (N_NODES + 63) / 64;       // 782
    const int AG = (N_NODES + 31) / 32;       // 1563

    k_zero_meta<<<NB_SCAN, 256>>>(ei32);
    k_hist<<<EG, 256>>>(ei32);
    k_s1<<<NB_SCAN, 256>>>();
    k_s2<<<1, 256>>>();
    k_s3<<<NB_SCAN, 256>>>();
    k_fill<<<EG, 256>>>(ei32, ew);

    k_gemm1<<<GG, 128>>>(x, W1);                 // g_h = half(x@W1)
    k_gather<<<AG, 256>>>(h, o1, b1, 1);         // g_o1 = relu(agg(g_h)+b1)
    k_gather<<<AG, 256>>>(o1, A, nullptr, 0);    // g_A = agg(g_o1)
    k_gemm2<<<GG, 128>>>(W2, b2, out);           // embed = A@W2+b2

    k_reduce<<<(N_NODES + 511) / 512, 256>>>(b32);
    k_gout<<<NUM_GRAPHS, F>>>(b32, W3, b3, out + (size_t)N_NODES * F);
}